// round 2
// baseline (speedup 1.0000x reference)
#include <cuda_runtime.h>
#include <cuda_bf16.h>

#define WARPS_PER_BLOCK 8
#define NT 32
#define MC 4
#define LOG2E 1.4426950408889634f

// One warp per batch element. Lane i owns row i of HH (32 regs) and the
// 4-element state G. Per-iteration xt broadcast goes through a 32-float
// shared stage read back as LDS.128 broadcasts (16B-aligned).
__global__ void __launch_bounds__(WARPS_PER_BLOCK * 32, 1)
cmdnet_kernel(const float* __restrict__ yt,
              const float* __restrict__ Ht,
              const float* __restrict__ sigmat0,
              const float* __restrict__ m_c,
              const float* __restrict__ alpha,
              const float* __restrict__ taui,
              const float* __restrict__ delta,
              float* __restrict__ out,
              int B, int NR, int NITER)
{
    __shared__ float s_scale[128];   // (ft_scale[i]) * LOG2E
    __shared__ float s_ta[128];      // |taui[i]|
    __shared__ float s_delta[128];
    __shared__ float s_tauN;         // |taui[NITER]| * LOG2E
    __shared__ __align__(16) float s_stage[WARPS_PER_BLOCK][8][NT];
    __shared__ __align__(16) float s_xt[WARPS_PER_BLOCK][NT];

    const int tid   = threadIdx.x;
    const int wslot = tid >> 5;
    const int lane  = tid & 31;

    if (tid < NITER) {
        float ta = fabsf(taui[tid]);
        s_ta[tid]    = ta;
        s_scale[tid] = ((tid == 0) ? 1.0f : ta) * LOG2E;   // first_iter scale = 1
        s_delta[tid] = delta[tid];
    }
    if (tid == 0) s_tauN = fabsf(taui[NITER]) * LOG2E;
    __syncthreads();

    const int b = blockIdx.x * WARPS_PER_BLOCK + wslot;
    if (b >= B) return;

    const float* Hb = Ht + (size_t)b * NR * NT;
    const float* yb = yt + (size_t)b * NR;

    // ---------------- Phase 1: HH row (per lane) + yH ----------------
    float hh[NT];
    #pragma unroll
    for (int k = 0; k < NT; k++) hh[k] = 0.0f;
    float yH = 0.0f;

    for (int r0 = 0; r0 < NR; r0 += 8) {
        float h[8];
        #pragma unroll
        for (int rr = 0; rr < 8; rr++) {
            h[rr] = Hb[(r0 + rr) * NT + lane];          // coalesced 128B/row
            s_stage[wslot][rr][lane] = h[rr];
            yH = fmaf(yb[r0 + rr], h[rr], yH);           // broadcast LDG
        }
        __syncwarp();
        #pragma unroll
        for (int rr = 0; rr < 8; rr++) {
            #pragma unroll
            for (int kk = 0; kk < 8; kk++) {
                float4 v = *reinterpret_cast<const float4*>(&s_stage[wslot][rr][4 * kk]);
                hh[4 * kk + 0] = fmaf(h[rr], v.x, hh[4 * kk + 0]);
                hh[4 * kk + 1] = fmaf(h[rr], v.y, hh[4 * kk + 1]);
                hh[4 * kk + 2] = fmaf(h[rr], v.z, hh[4 * kk + 2]);
                hh[4 * kk + 3] = fmaf(h[rr], v.w, hh[4 * kk + 3]);
            }
        }
        __syncwarp();
    }

    // ---------------- Phase 2: 64 iterations ----------------
    float la[MC], mj[MC];
    #pragma unroll
    for (int j = 0; j < MC; j++) {
        la[j] = logf(alpha[j]);     // natural log, matches reference
        mj[j] = m_c[j];
    }
    float G[MC] = {0.0f, 0.0f, 0.0f, 0.0f};
    float sig2;
    { float s = sigmat0[b]; sig2 = s * s; }

    float f[MC];
    float xt = 0.0f;

    for (int it = 0; it < NITER; it++) {
        const float sc = s_scale[it];

        // softmax((la + G) * scale) in log2 domain: one MUFU.EX2 per term
        float z[MC];
        #pragma unroll
        for (int j = 0; j < MC; j++) z[j] = (la[j] + G[j]) * sc;
        float mx = fmaxf(fmaxf(z[0], z[1]), fmaxf(z[2], z[3]));
        float e[MC];
        #pragma unroll
        for (int j = 0; j < MC; j++) e[j] = exp2f(z[j] - mx);
        float sum = (e[0] + e[1]) + (e[2] + e[3]);
        float inv = __fdividef(1.0f, sum);
        #pragma unroll
        for (int j = 0; j < MC; j++) f[j] = e[j] * inv;

        // soft symbol
        xt = f[0] * mj[0];
        #pragma unroll
        for (int j = 1; j < MC; j++) xt = fmaf(f[j], mj[j], xt);

        // broadcast xt across the warp via shared, then xHH = xt . HH[:,lane]
        __syncwarp();
        s_xt[wslot][lane] = xt;
        __syncwarp();
        float acc = 0.0f;
        #pragma unroll
        for (int kk = 0; kk < 8; kk++) {
            float4 v = *reinterpret_cast<const float4*>(&s_xt[wslot][4 * kk]);
            acc = fmaf(v.x, hh[4 * kk + 0], acc);
            acc = fmaf(v.y, hh[4 * kk + 1], acc);
            acc = fmaf(v.z, hh[4 * kk + 2], acc);
            acc = fmaf(v.w, hh[4 * kk + 3], acc);
        }

        // grad_L = sig2*(1 - exp(-G)) + ta*(xHH - yH) * ft*(m - xt)
        const float c = s_ta[it] * (acc - yH);
        const float d = s_delta[it];
        #pragma unroll
        for (int j = 0; j < MC; j++) {
            float eg = exp2f(G[j] * (-LOG2E));          // exp(-G)
            float t  = fmaf(-sig2, eg, sig2);           // sig2*(1-eg)
            float w  = f[j] * (mj[j] - xt);
            float gl = fmaf(c, w, t);
            G[j] = fmaf(-d, gl, G[j]);
        }
    }

    // ---------------- Final layer: softmax + soft symbol, no update ----------------
    {
        const float sc = s_tauN;
        float z[MC];
        #pragma unroll
        for (int j = 0; j < MC; j++) z[j] = (la[j] + G[j]) * sc;
        float mx = fmaxf(fmaxf(z[0], z[1]), fmaxf(z[2], z[3]));
        float e[MC];
        #pragma unroll
        for (int j = 0; j < MC; j++) e[j] = exp2f(z[j] - mx);
        float sum = (e[0] + e[1]) + (e[2] + e[3]);
        float inv = __fdividef(1.0f, sum);
        #pragma unroll
        for (int j = 0; j < MC; j++) f[j] = e[j] * inv;
        xt = f[0] * mj[0];
        #pragma unroll
        for (int j = 1; j < MC; j++) xt = fmaf(f[j], mj[j], xt);
    }

    // ---------------- Write out: ft [B,NT,MC] then xt [B,NT] ----------------
    const size_t base = (size_t)b * NT + lane;
    float4 o;
    o.x = f[0]; o.y = f[1]; o.z = f[2]; o.w = f[3];
    *reinterpret_cast<float4*>(&out[base * MC]) = o;     // 16B-aligned, coalesced
    out[(size_t)B * NT * MC + base] = xt;
}

extern "C" void kernel_launch(void* const* d_in, const int* in_sizes, int n_in,
                              void* d_out, int out_size)
{
    const float* yt     = (const float*)d_in[0];
    const float* Ht     = (const float*)d_in[1];
    const float* sig    = (const float*)d_in[2];
    const float* m      = (const float*)d_in[3];
    const float* alpha  = (const float*)d_in[4];
    const float* taui   = (const float*)d_in[5];
    const float* delta  = (const float*)d_in[6];

    const int B     = in_sizes[2];
    const int NR    = in_sizes[0] / B;
    const int NITER = in_sizes[6];

    const int blocks = (B + WARPS_PER_BLOCK - 1) / WARPS_PER_BLOCK;
    cmdnet_kernel<<<blocks, WARPS_PER_BLOCK * 32>>>(
        yt, Ht, sig, m, alpha, taui, delta, (float*)d_out, B, NR, NITER);
}